// round 16
// baseline (speedup 1.0000x reference)
#include <cuda_runtime.h>
#include <math.h>

#define BB 256
#define QQ 300
#define GG 16
#define KMAX 10    // ceil(QQ/32) columns per lane
#define HTHR 320   // threads per half (one q per thread)
#define NTHR 640   // two batches per block
#define NW 10      // warps per half

#define SCR_W 25                            // 24 logits + pad, stride 25 (coprime to 32)
#define HALF_FLOATS (QQ * SCR_W + GG * QQ)  // 7500 + 4800 = 12300 per half
#define DYN_BYTES (2 * HALF_FLOATS * 4)     // 98400

// ---------------- device scratch (no allocations allowed) ----------------
__device__ double   g_l1[BB];
__device__ double   g_bce[BB];
__device__ int      g_cnt[BB];
__device__ unsigned g_done = 0;           // counts LAP warps (2 per block); last resets

__constant__ float c_tw[32] = {
    1.17236407f, 1.0166286f, 1.19620973f, 0.5544405f, 0.63531401f, 0.51258428f,
    1.08866652f, 1.15795989f, 1.07389395f, 0.98728399f, 1.12754142f, 1.05953744f,
    1.16945323f, 1.15512349f, 1.02097204f, 1.15795989f, 1.07147279f, 0.50627649f,
    1.07147279f, 0.61697221f, 1.16367678f, 1.0231585f, 1.18416106f, 1.04329092f,
    1.10645159f, 1.18416106f, 1.15795989f, 1.16367678f, 0.73949534f, 0.78760821f,
    1.08617476f, 1.00805777f
};

// order-preserving float <-> u32 key (finite + inf safe)
__device__ __forceinline__ unsigned f2key(float f) {
    unsigned u = __float_as_uint(f);
    return (u & 0x80000000u) ? ~u : (u | 0x80000000u);
}
__device__ __forceinline__ float key2f(unsigned k) {
    unsigned u = (k & 0x80000000u) ? (k & 0x7fffffffu) : ~k;
    return __uint_as_float(u);
}

// warp argmin (value, lowest index among minima)
__device__ __forceinline__ void warp_argmin(float val, int idx, float& mval, int& midx) {
    const unsigned mykey = f2key(val);
    const unsigned mkey  = __reduce_min_sync(0xffffffffu, mykey);
    const unsigned cand  = (mykey == mkey) ? (unsigned)idx : 0xffffffffu;
    midx = (int)__reduce_min_sync(0xffffffffu, cand);
    mval = key2f(mkey);
}

// ---- fused kernel: 2 batches per block ----
__global__ __launch_bounds__(NTHR, 1) void fused_kernel(
    const float* __restrict__ ph,
    const float* __restrict__ pr,
    const float* __restrict__ pt,
    const float* __restrict__ IVT,
    const int* __restrict__ iid,
    const int* __restrict__ vid,
    const int* __restrict__ tgt,
    const int* __restrict__ triplet,
    const int* __restrict__ mask,
    float* __restrict__ out)
{
    const int tid  = threadIdx.x;
    const int half = (tid >= HTHR) ? 1 : 0;
    const int ltid = tid - half * HTHR;       // 0..319 within the half
    const int lwrp = ltid >> 5;               // 0..9 within the half
    const int lane = tid & 31;
    const int b    = blockIdx.x * 2 + half;   // this half's batch

    extern __shared__ float dyn[];
    float* s_scr = dyn + half * HALF_FLOATS;                // [QQ][SCR_W]
    float* Cm    = dyn + half * HALF_FLOATS + QQ * SCR_W;   // [GG][QQ]

    __shared__ unsigned long long s_part[2][GG][NW];
    __shared__ float s_u[2][GG + 1];
    __shared__ int   s_p[2][QQ + 1];
    __shared__ int   s_way[2][QQ + 1];
    __shared__ int   si[2][GG], sv[2][GG], st[2][GG];
    __shared__ int   s_unass[2][GG];

    // ---- phase 0: first warp of each half computes its batch's BCE (overlapped) ----
    double bce_row = 0.0;
    if (lwrp == 0) {
        float x = IVT[b * 32 + lane];
        float t = (float)triplet[b * 32 + lane];
        float v = fmaxf(x, 0.f) - x * t + log1pf(__expf(-fabsf(x)));
        bce_row = (double)(c_tw[lane] * v);
#pragma unroll
        for (int off = 16; off > 0; off >>= 1)
            bce_row += __shfl_down_sync(0xffffffffu, bce_row, off);
    }

    if (ltid < GG) {
        si[half][ltid] = iid[b * GG + ltid];
        sv[half][ltid] = vid[b * GG + ltid];
        st[half][ltid] = tgt[b * GG + ltid];
    }
    for (int j = ltid; j <= QQ; j += HTHR) { s_p[half][j] = 0; s_way[half][j] = 0; }
    if (ltid <= GG) s_u[half][ltid] = 0.f;
    __syncthreads();

    // ---- phase 1: logits -> shared scratch + direct log-sum-exp ----
    if (ltid < QQ) {
        const int q = ltid;
        float* scr = s_scr + q * SCR_W;
        const float* hp = ph + (size_t)(b * QQ + q) * 9;
        const float* rp = pr + (size_t)(b * QQ + q) * 13;
        const float* tp = pt + (size_t)(b * QQ + q) * 2;

        float sh = 0.f, sr = 0.f, stt = 0.f;
#pragma unroll
        for (int i = 0; i < 9; i++)  { float x = hp[i]; scr[i]      = x; sh  += __expf(x); }
#pragma unroll
        for (int i = 0; i < 13; i++) { float x = rp[i]; scr[9 + i]  = x; sr  += __expf(x); }
#pragma unroll
        for (int i = 0; i < 2; i++)  { float x = tp[i]; scr[22 + i] = x; stt += __expf(x); }

        const float lsum = __logf(sh) + __logf(sr) + __logf(stt);
        scr[24] = lsum;

#pragma unroll
        for (int g = 0; g < GG; g++) {
            Cm[g * QQ + q] = lsum - (scr[si[half][g]] + scr[9 + sv[half][g]] + scr[22 + st[half][g]]);
        }
    }
    __syncthreads();

    // ---- phase 1b: 10 warps per half compute row minima in parallel ----
#pragma unroll
    for (int rr = 0; rr < 2; rr++) {
        const int row = lwrp + NW * rr;       // rows 0..15 over warps 0..9
        if (row < GG) {
            const float* Crow = Cm + row * QQ;
            float best = INFINITY;
            int   bidx = QQ + 2;
#pragma unroll
            for (int k = 0; k < KMAX; k++) {
                int j = 1 + lane + 32 * k;
                if (j <= QQ) {
                    float c = Crow[j - 1];
                    if (c < best) { best = c; bidx = j; }
                }
            }
            float rmin; int jm;
            warp_argmin(best, bidx, rmin, jm);
            if (lane == 0)
                s_part[half][row][0] = ((unsigned long long)f2key(rmin) << 32) | (unsigned)jm;
        }
    }
    __syncthreads();

    // ---- phase 2: first warp of each half solves its LAP ----
    if (lwrp != 0) return;

    float rmin_l = 0.f; int jm_l = 0;
    if (lane < GG) {
        unsigned long long m = s_part[half][lane][0];
        rmin_l = key2f((unsigned)(m >> 32));
        jm_l   = (int)(m & 0xffffffffu);
    }

    unsigned mb = __ballot_sync(0xffffffffu, lane < GG && mask[b * GG + lane] != 0);
    const int n = __popc(mb);

    float v[KMAX], minv[KMAX];
#pragma unroll
    for (int k = 0; k < KMAX; k++) v[k] = 0.f;

    // -- phase 2a: greedy init from row minima --
    int n_unass = 0;
    for (int i = 1; i <= n; i++) {
        float ru = __shfl_sync(0xffffffffu, rmin_l, i - 1);
        int   jm = __shfl_sync(0xffffffffu, jm_l,   i - 1);
        if (lane == 0) {
            s_u[half][i] = ru;
            if (s_p[half][jm] == 0) s_p[half][jm] = i;
            else                    s_unass[half][n_unass++] = i;
        }
    }
    n_unass = __shfl_sync(0xffffffffu, n_unass, 0);
    __syncwarp();

    // -- phase 2b: Dijkstra augmentation for unassigned rows only --
    for (int ui = 0; ui < n_unass; ui++) {
        const int i = s_unass[half][ui];
#pragma unroll
        for (int k = 0; k < KMAX; k++) minv[k] = INFINITY;
        unsigned used = 0;
        int j0 = 0;
        if (lane == 0) s_p[half][0] = i;
        __syncwarp();

        while (true) {
            if (j0 > 0 && (((j0 - 1) & 31) == lane))
                used |= 1u << ((j0 - 1) >> 5);

            const int   i0   = s_p[half][j0];
            const float u_i0 = s_u[half][i0];
            const float* Crow = Cm + (i0 - 1) * QQ;

            float best = INFINITY;
            int   bidx = QQ + 2;
#pragma unroll
            for (int k = 0; k < KMAX; k++) {
                int j = 1 + lane + 32 * k;
                if (j <= QQ && !((used >> k) & 1u)) {
                    float cur = Crow[j - 1] - u_i0 - v[k];
                    if (cur < minv[k]) { minv[k] = cur; s_way[half][j] = j0; }
                    if (minv[k] < best) { best = minv[k]; bidx = j; }
                }
            }
            float delta; int j1;
            warp_argmin(best, bidx, delta, j1);

#pragma unroll
            for (int k = 0; k < KMAX; k++) {
                int j = 1 + lane + 32 * k;
                if (j <= QQ) {
                    if ((used >> k) & 1u) {
                        v[k] -= delta;
                        s_u[half][s_p[half][j]] += delta;  // distinct p[j] across used cols
                    } else {
                        minv[k] -= delta;
                    }
                }
            }
            if (lane == 0) s_u[half][i] += delta;          // virtual column 0
            __syncwarp();

            if (s_p[half][j1] == 0) { j0 = j1; break; }
            j0 = j1;
        }

        if (lane == 0) {
            int jj = j0;
            while (jj) {
                int jp = s_way[half][jj];
                s_p[half][jj] = s_p[half][jp];
                jj = jp;
            }
        }
        __syncwarp();
    }

    // sum selected float32 costs (optimal total is assignment-independent)
    double local = 0.0;
#pragma unroll
    for (int k = 0; k < KMAX; k++) {
        int j = 1 + lane + 32 * k;
        if (j <= QQ) {
            int pj = s_p[half][j];
            if (pj > 0) local += (double)Cm[(pj - 1) * QQ + (j - 1)];
        }
    }
#pragma unroll
    for (int off = 16; off > 0; off >>= 1)
        local += __shfl_down_sync(0xffffffffu, local, off);
    if (lane == 0) {
        g_l1[b]  = local;
        g_cnt[b] = n;
        g_bce[b] = bce_row;
    }

    // ---- phase 3: last LAP warp performs the final combine (deterministic order) ----
    __threadfence();
    unsigned old = 0;
    if (lane == 0) old = atomicAdd(&g_done, 1u);
    old = __shfl_sync(0xffffffffu, old, 0);
    if (old == BB - 1) {
        double l1 = 0.0, cnt = 0.0, bce = 0.0;
#pragma unroll
        for (int k = 0; k < BB / 32; k++) {
            int bb = lane + 32 * k;
            l1  += __ldcg(&g_l1[bb]);
            cnt += (double)__ldcg(&g_cnt[bb]);
            bce += __ldcg(&g_bce[bb]);
        }
#pragma unroll
        for (int off = 16; off > 0; off >>= 1) {
            l1  += __shfl_down_sync(0xffffffffu, l1, off);
            cnt += __shfl_down_sync(0xffffffffu, cnt, off);
            bce += __shfl_down_sync(0xffffffffu, bce, off);
        }
        if (lane == 0) {
            double loss1 = l1 / cnt;
            double loss5 = bce / (double)(BB * 32);
            out[0] = (float)(0.1 * loss1 + 1.0 * loss5);
            g_done = 0;                      // reset for next graph replay
        }
    }
}

// ---------------- launch ----------------
extern "C" void kernel_launch(void* const* d_in, const int* in_sizes, int n_in,
                              void* d_out, int out_size) {
    const float* pred_head = (const float*)d_in[0];
    const float* pred_rel  = (const float*)d_in[1];
    const float* pred_tail = (const float*)d_in[2];
    const float* IVT       = (const float*)d_in[3];
    const int*   iid       = (const int*)d_in[4];
    const int*   vid       = (const int*)d_in[5];
    const int*   tgt       = (const int*)d_in[6];
    // d_in[7..9] (instrument, verb, target) unused by the reference
    const int*   triplet   = (const int*)d_in[10];
    const int*   mask      = (const int*)d_in[11];
    float* out = (float*)d_out;

    static bool attr_set = false;
    if (!attr_set) {
        cudaFuncSetAttribute(fused_kernel,
                             cudaFuncAttributeMaxDynamicSharedMemorySize, DYN_BYTES);
        attr_set = true;
    }

    fused_kernel<<<BB / 2, NTHR, DYN_BYTES>>>(pred_head, pred_rel, pred_tail, IVT,
                                              iid, vid, tgt, triplet, mask, out);
}

// round 17
// speedup vs baseline: 1.0865x; 1.0865x over previous
#include <cuda_runtime.h>
#include <math.h>

#define BB 256
#define QQ 300
#define GG 16
#define KMAX 10   // ceil(QQ/32) columns per lane
#define NTHR 320  // one q per thread in phase 1; 10 warps
#define NW 10

#define SCR_W 25                           // 24 logits + pad, stride 25 (coprime to 32)
#define DYN_FLOATS (QQ * SCR_W + GG * QQ)  // 7500 + 4800 = 12300
#define DYN_BYTES (DYN_FLOATS * 4)         // 49200

// ---------------- device scratch (no allocations allowed) ----------------
__device__ double   g_l1[BB];
__device__ double   g_bce[BB];
__device__ int      g_cnt[BB];
__device__ unsigned g_done = 0;

__constant__ float c_tw[32] = {
    1.17236407f, 1.0166286f, 1.19620973f, 0.5544405f, 0.63531401f, 0.51258428f,
    1.08866652f, 1.15795989f, 1.07389395f, 0.98728399f, 1.12754142f, 1.05953744f,
    1.16945323f, 1.15512349f, 1.02097204f, 1.15795989f, 1.07147279f, 0.50627649f,
    1.07147279f, 0.61697221f, 1.16367678f, 1.0231585f, 1.18416106f, 1.04329092f,
    1.10645159f, 1.18416106f, 1.15795989f, 1.16367678f, 0.73949534f, 0.78760821f,
    1.08617476f, 1.00805777f
};

// order-preserving float <-> u32 key (finite + inf safe)
__device__ __forceinline__ unsigned f2key(float f) {
    unsigned u = __float_as_uint(f);
    return (u & 0x80000000u) ? ~u : (u | 0x80000000u);
}
__device__ __forceinline__ float key2f(unsigned k) {
    unsigned u = (k & 0x80000000u) ? (k & 0x7fffffffu) : ~k;
    return __uint_as_float(u);
}

__device__ __forceinline__ void warp_argmin(float val, int idx, float& mval, int& midx) {
    const unsigned mykey = f2key(val);
    const unsigned mkey  = __reduce_min_sync(0xffffffffu, mykey);
    const unsigned cand  = (mykey == mkey) ? (unsigned)idx : 0xffffffffu;
    midx = (int)__reduce_min_sync(0xffffffffu, cand);
    mval = key2f(mkey);
}

// ---- packed f32x2 exp on the FMA/ALU pipes (runs concurrently with MUFU) ----
// exp(x) = 2^(x*log2e); magic-constant round, degree-5 poly on t in [-0.5,0.5].
__device__ __forceinline__ unsigned long long splat2(float v) {
    unsigned long long r;
    asm("mov.b64 %0, {%1, %2};" : "=l"(r) : "f"(v), "f"(v));
    return r;
}
__device__ __forceinline__ void exp_pair(float a, float b, float& ea, float& eb) {
    const unsigned long long L2E  = splat2(1.4426950408889634f);
    const unsigned long long MAG  = splat2(12582912.0f);     // 2^23 + 2^22
    const unsigned long long NMAG = splat2(-12582912.0f);
    const unsigned long long NONE = splat2(-1.0f);
    const unsigned long long C5   = splat2(1.33335581e-3f);
    const unsigned long long C4   = splat2(9.61812911e-3f);
    const unsigned long long C3   = splat2(5.55041087e-2f);
    const unsigned long long C2   = splat2(2.40226507e-1f);
    const unsigned long long C1   = splat2(6.93147181e-1f);
    const unsigned long long C0   = splat2(1.0f);

    unsigned long long x, y, z, f, t, p, s, r;
    asm("mov.b64 %0, {%1, %2};" : "=l"(x) : "f"(a), "f"(b));
    asm("mul.rn.f32x2 %0, %1, %2;" : "=l"(y) : "l"(x), "l"(L2E));
    asm("add.rn.f32x2 %0, %1, %2;" : "=l"(z) : "l"(y), "l"(MAG));   // round to int in mantissa
    asm("add.rn.f32x2 %0, %1, %2;" : "=l"(f) : "l"(z), "l"(NMAG));  // f = round(y)
    asm("fma.rn.f32x2 %0, %1, %2, %3;" : "=l"(t) : "l"(f), "l"(NONE), "l"(y)); // t = y - f
    p = C5;
    asm("fma.rn.f32x2 %0, %1, %2, %3;" : "=l"(p) : "l"(p), "l"(t), "l"(C4));
    asm("fma.rn.f32x2 %0, %1, %2, %3;" : "=l"(p) : "l"(p), "l"(t), "l"(C3));
    asm("fma.rn.f32x2 %0, %1, %2, %3;" : "=l"(p) : "l"(p), "l"(t), "l"(C2));
    asm("fma.rn.f32x2 %0, %1, %2, %3;" : "=l"(p) : "l"(p), "l"(t), "l"(C1));
    asm("fma.rn.f32x2 %0, %1, %2, %3;" : "=l"(p) : "l"(p), "l"(t), "l"(C0));
    // scale by 2^i: bits(z) = bits(MAG) + i; (bits << 23) + one_bits == float(2^i)
    unsigned zl, zh;
    asm("mov.b64 {%0, %1}, %2;" : "=r"(zl), "=r"(zh) : "l"(z));
    unsigned sl = (zl << 23) + 0x3F800000u;
    unsigned sh = (zh << 23) + 0x3F800000u;
    asm("mov.b64 %0, {%1, %2};" : "=l"(s) : "r"(sl), "r"(sh));
    asm("mul.rn.f32x2 %0, %1, %2;" : "=l"(r) : "l"(p), "l"(s));
    asm("mov.b64 {%0, %1}, %2;" : "=f"(ea), "=f"(eb) : "l"(r));
}

// ---- fused kernel (R12 champion shape; only phase-1 exp path changed) ----
__global__ __launch_bounds__(NTHR) void fused_kernel(
    const float* __restrict__ ph,
    const float* __restrict__ pr,
    const float* __restrict__ pt,
    const float* __restrict__ IVT,
    const int* __restrict__ iid,
    const int* __restrict__ vid,
    const int* __restrict__ tgt,
    const int* __restrict__ triplet,
    const int* __restrict__ mask,
    float* __restrict__ out)
{
    const int b   = blockIdx.x;
    const int tid = threadIdx.x;
    const int wid = tid >> 5;

    extern __shared__ float dyn[];
    float* s_scr = dyn;                  // [QQ][SCR_W]
    float* Cm    = dyn + QQ * SCR_W;     // [GG][QQ]

    __shared__ float s_u[GG + 1];
    __shared__ int   s_p[QQ + 1];
    __shared__ int   s_way[QQ + 1];
    __shared__ int   si[GG], sv[GG], st[GG];
    __shared__ int   s_unass[GG];
    __shared__ float s_rmin[GG];
    __shared__ int   s_jm[GG];

    // ---- phase 0: warp 0 computes this batch row's weighted BCE ----
    double bce_row = 0.0;
    if (tid < 32) {
        float x = IVT[b * 32 + tid];
        float t = (float)triplet[b * 32 + tid];
        float v = fmaxf(x, 0.f) - x * t + log1pf(__expf(-fabsf(x)));
        bce_row = (double)(c_tw[tid] * v);
#pragma unroll
        for (int off = 16; off > 0; off >>= 1)
            bce_row += __shfl_down_sync(0xffffffffu, bce_row, off);
    }

    if (tid < GG) {
        si[tid] = iid[b * GG + tid];
        sv[tid] = vid[b * GG + tid];
        st[tid] = tgt[b * GG + tid];
    }
    for (int j = tid; j <= QQ; j += NTHR) { s_p[j] = 0; s_way[j] = 0; }
    if (tid <= GG) s_u[tid] = 0.f;
    __syncthreads();

    // ---- phase 1: logits -> scr; exps split MUFU / packed-FMA; lsum; costs ----
    if (tid < QQ) {
        const int q = tid;
        float* scr = s_scr + q * SCR_W;
        const float* hp = ph + (size_t)(b * QQ + q) * 9;
        const float* rp = pr + (size_t)(b * QQ + q) * 13;
        const float* tp = pt + (size_t)(b * QQ + q) * 2;

        float hv[9], rv[13], tv[2];
#pragma unroll
        for (int i = 0; i < 9; i++)  { hv[i] = hp[i]; scr[i]      = hv[i]; }
#pragma unroll
        for (int i = 0; i < 13; i++) { rv[i] = rp[i]; scr[9 + i]  = rv[i]; }
#pragma unroll
        for (int i = 0; i < 2; i++)  { tv[i] = tp[i]; scr[22 + i] = tv[i]; }

        float ea, eb;
        // packed poly path (FMA/ALU pipes): h[0..1], r[0..11]  -> 7 pairs
        float sh, sr, stt;
        exp_pair(hv[0], hv[1], ea, eb);   sh = ea + eb;
        exp_pair(rv[0], rv[1], ea, eb);   sr = ea + eb;
        exp_pair(rv[2], rv[3], ea, eb);   sr += ea + eb;
        exp_pair(rv[4], rv[5], ea, eb);   sr += ea + eb;
        exp_pair(rv[6], rv[7], ea, eb);   sr += ea + eb;
        exp_pair(rv[8], rv[9], ea, eb);   sr += ea + eb;
        exp_pair(rv[10], rv[11], ea, eb); sr += ea + eb;
        // MUFU path: h[2..8], r[12], t[0..1], 3 logs
#pragma unroll
        for (int i = 2; i < 9; i++) sh += __expf(hv[i]);
        sr += __expf(rv[12]);
        stt = __expf(tv[0]) + __expf(tv[1]);

        const float lsum = __logf(sh) + __logf(sr) + __logf(stt);
        scr[24] = lsum;

#pragma unroll
        for (int g = 0; g < GG; g++) {
            Cm[g * QQ + q] = lsum - (scr[si[g]] + scr[9 + sv[g]] + scr[22 + st[g]]);
        }
    }
    __syncthreads();

    // ---- phase 1b: all 10 warps compute row minima in parallel ----
    {
        const int lane = tid & 31;
#pragma unroll
        for (int rr = 0; rr < 2; rr++) {
            const int row = wid + NW * rr;
            if (row < GG) {
                const float* Crow = Cm + row * QQ;
                float best = INFINITY;
                int   bidx = QQ + 2;
#pragma unroll
                for (int k = 0; k < KMAX; k++) {
                    int j = 1 + lane + 32 * k;
                    if (j <= QQ) {
                        float c = Crow[j - 1];
                        if (c < best) { best = c; bidx = j; }
                    }
                }
                float rmin; int jm;
                warp_argmin(best, bidx, rmin, jm);
                if (lane == 0) { s_rmin[row] = rmin; s_jm[row] = jm; }
            }
        }
    }
    __syncthreads();

    // ---- phase 2: warp 0 solves the LAP ----
    if (tid >= 32) return;
    const int lane = tid;

    unsigned mb = __ballot_sync(0xffffffffu, lane < GG && mask[b * GG + lane] != 0);
    const int n = __popc(mb);

    float v[KMAX], minv[KMAX];
#pragma unroll
    for (int k = 0; k < KMAX; k++) v[k] = 0.f;

    // -- phase 2a: greedy init from precomputed row minima --
    int n_unass = 0;
    if (lane == 0) {
        for (int i = 1; i <= n; i++) {
            s_u[i] = s_rmin[i - 1];
            int jm = s_jm[i - 1];
            if (s_p[jm] == 0) s_p[jm] = i;
            else              s_unass[n_unass++] = i;
        }
    }
    n_unass = __shfl_sync(0xffffffffu, n_unass, 0);
    __syncwarp();

    // -- phase 2b: Dijkstra augmentation for unassigned rows only --
    for (int ui = 0; ui < n_unass; ui++) {
        const int i = s_unass[ui];
#pragma unroll
        for (int k = 0; k < KMAX; k++) minv[k] = INFINITY;
        unsigned used = 0;
        int j0 = 0;
        if (lane == 0) s_p[0] = i;
        __syncwarp();

        while (true) {
            if (j0 > 0 && (((j0 - 1) & 31) == lane))
                used |= 1u << ((j0 - 1) >> 5);

            const int   i0   = s_p[j0];
            const float u_i0 = s_u[i0];
            const float* Crow = Cm + (i0 - 1) * QQ;

            float best = INFINITY;
            int   bidx = QQ + 2;
#pragma unroll
            for (int k = 0; k < KMAX; k++) {
                int j = 1 + lane + 32 * k;
                if (j <= QQ && !((used >> k) & 1u)) {
                    float cur = Crow[j - 1] - u_i0 - v[k];
                    if (cur < minv[k]) { minv[k] = cur; s_way[j] = j0; }
                    if (minv[k] < best) { best = minv[k]; bidx = j; }
                }
            }
            float delta; int j1;
            warp_argmin(best, bidx, delta, j1);

#pragma unroll
            for (int k = 0; k < KMAX; k++) {
                int j = 1 + lane + 32 * k;
                if (j <= QQ) {
                    if ((used >> k) & 1u) {
                        v[k] -= delta;
                        s_u[s_p[j]] += delta;
                    } else {
                        minv[k] -= delta;
                    }
                }
            }
            if (lane == 0) s_u[i] += delta;
            __syncwarp();

            if (s_p[j1] == 0) { j0 = j1; break; }
            j0 = j1;
        }

        if (lane == 0) {
            int jj = j0;
            while (jj) {
                int jp = s_way[jj];
                s_p[jj] = s_p[jp];
                jj = jp;
            }
        }
        __syncwarp();
    }

    // sum selected float32 costs
    double local = 0.0;
#pragma unroll
    for (int k = 0; k < KMAX; k++) {
        int j = 1 + lane + 32 * k;
        if (j <= QQ) {
            int pj = s_p[j];
            if (pj > 0) local += (double)Cm[(pj - 1) * QQ + (j - 1)];
        }
    }
#pragma unroll
    for (int off = 16; off > 0; off >>= 1)
        local += __shfl_down_sync(0xffffffffu, local, off);
    if (lane == 0) {
        g_l1[b]  = local;
        g_cnt[b] = n;
        g_bce[b] = bce_row;
    }

    // ---- phase 3: last block performs the final combine ----
    __threadfence();
    unsigned old = 0;
    if (lane == 0) old = atomicAdd(&g_done, 1u);
    old = __shfl_sync(0xffffffffu, old, 0);
    if (old == BB - 1) {
        double l1 = 0.0, cnt = 0.0, bce = 0.0;
#pragma unroll
        for (int k = 0; k < BB / 32; k++) {
            int bb = lane + 32 * k;
            l1  += __ldcg(&g_l1[bb]);
            cnt += (double)__ldcg(&g_cnt[bb]);
            bce += __ldcg(&g_bce[bb]);
        }
#pragma unroll
        for (int off = 16; off > 0; off >>= 1) {
            l1  += __shfl_down_sync(0xffffffffu, l1, off);
            cnt += __shfl_down_sync(0xffffffffu, cnt, off);
            bce += __shfl_down_sync(0xffffffffu, bce, off);
        }
        if (lane == 0) {
            double loss1 = l1 / cnt;
            double loss5 = bce / (double)(BB * 32);
            out[0] = (float)(0.1 * loss1 + 1.0 * loss5);
            g_done = 0;
        }
    }
}

// ---------------- launch ----------------
extern "C" void kernel_launch(void* const* d_in, const int* in_sizes, int n_in,
                              void* d_out, int out_size) {
    const float* pred_head = (const float*)d_in[0];
    const float* pred_rel  = (const float*)d_in[1];
    const float* pred_tail = (const float*)d_in[2];
    const float* IVT       = (const float*)d_in[3];
    const int*   iid       = (const int*)d_in[4];
    const int*   vid       = (const int*)d_in[5];
    const int*   tgt       = (const int*)d_in[6];
    const int*   triplet   = (const int*)d_in[10];
    const int*   mask      = (const int*)d_in[11];
    float* out = (float*)d_out;

    static bool attr_set = false;
    if (!attr_set) {
        cudaFuncSetAttribute(fused_kernel,
                             cudaFuncAttributeMaxDynamicSharedMemorySize, DYN_BYTES);
        attr_set = true;
    }

    fused_kernel<<<BB, NTHR, DYN_BYTES>>>(pred_head, pred_rel, pred_tail, IVT,
                                          iid, vid, tgt, triplet, mask, out);
}